// round 12
// baseline (speedup 1.0000x reference)
#include <cuda_runtime.h>
#include <math.h>
#include <stdint.h>

// Problem constants
#define BB 128
#define NN 2000
#define CC 100
#define DD 128
#define HH 8
#define NEGV (-1000000000.0f)
#define CLIPV 10.0f

#define SPLIT 20
#define CH (NN / SPLIT)       // 100 nodes per chunk
#define PRE_CTAS 96           // weight-folding CTAs (placed first in grid)
#define FOLD_ROWS 768         // PQ:0..383  Zt:384..511  ZV:512..639  ZW:640..767

// Output layout (float32, flattened tuple order)
#define OUT_AUG 0
#define OUT_GEMB 65536
#define OUT_GUID 81920
#define OUT_CLU 82048

// Global scratch
#define G2OFF (BB * SPLIT * DD)
__device__ float g_part[2 * BB * SPLIT * DD];   // partial masked sums
__device__ float g_fold[FOLD_ROWS * DD];        // folded weight products

// ---------------- Kernel 2 shared memory layout (float offsets) -------------
#define S_CS   0        // cluster tile [100][129]
#define S_ZT   12900    // Zt staged [128][128]
#define S_ZV   29284    // ZV staged [128][128]
#define S_PB   45668    // warp partials [16][132]
#define S_M1   47780
#define S_M2   47908
#define S_CUR  48036
#define S_DEP  48164
#define S_CTX  48292    // [384]
#define S_QH   48676
#define S_U4   48804    // u packed [128][8]
#define S_SCP  49828    // score partials [100][33]
#define S_AT4  53128    // attn packed [100][8]
#define S_WS4  53928    // wsum packed [128][8]
#define S_GV   54952
#define S_GW   55080
#define S_PART 55208    // [100][2] + pad
#define S_LGT  55416
#define S_MISC 55520
#define S_VCM  55524
#define SMEM_FLOATS 55632
#define SMEM_BYTES (SMEM_FLOATS * 4)

__device__ __forceinline__ bool rdmask(const void* p, int flag, long long i) {
    if (flag == 0) return ((const unsigned char*)p)[i] != 0;
    if (flag == 1) return ((const int*)p)[i] != 0;
    return ((const float*)p)[i] != 0.0f;
}

__device__ __forceinline__ void cpasync16(uint32_t saddr, const void* g) {
    asm volatile("cp.async.cg.shared.global [%0], [%1], 16;" :: "r"(saddr), "l"(g));
}
#define CP_COMMIT() asm volatile("cp.async.commit_group;")
#define CP_WAIT(n)  asm volatile("cp.async.wait_group %0;" :: "n"(n))

// ============================================================================
// Kernel 1: [blocks 0..95] weight folding  +  [blocks 96..] masked partial
// sums over node_embeddings. grid = PRE_CTAS + B*SPLIT.
// ============================================================================
__global__ void __launch_bounds__(256)
means_pre_kernel(const float* __restrict__ node, const void* __restrict__ maskp,
                 const void* __restrict__ cmaskp,
                 const float* __restrict__ Wq, const float* __restrict__ Wk,
                 const float* __restrict__ Wv, const float* __restrict__ Wks,
                 const float* __restrict__ Wmq, const float* __restrict__ Wmk,
                 const float* __restrict__ Wmv, const float* __restrict__ Wmo) {
    __shared__ float red[2 * 1024];
    __shared__ float a_sm[8 * 128];
    __shared__ unsigned char mloc[CH], cmloc[CH];
    const int t = threadIdx.x;
    const int lane = t & 31;
    const int w = t >> 5;

    // sniff bool serialization dtype (byte / int32 / float32)
    unsigned wword = ((const unsigned*)maskp)[t];
    int o1  = __syncthreads_or((wword & 0x0000ff00u) ? 1 : 0);
    int o23 = __syncthreads_or((wword & 0xffff0000u) ? 1 : 0);
    const int flag = o1 ? 0 : (o23 ? 2 : 1);

    if (blockIdx.x < PRE_CTAS) {
        // -------- weight folding: 8 output rows of the 768-row table --------
        const int r0 = blockIdx.x * 8;
        for (int idx = t; idx < 8 * 128; idx += 256) {
            int row = idx >> 7, j = idx & 127;
            int R = r0 + row;
            const float* A;
            if (R < 384)      A = Wq  + (size_t)R * DD;
            else if (R < 512) A = Wk  + (size_t)(R - 384) * DD;
            else if (R < 640) A = Wv  + (size_t)(R - 512) * DD;
            else              A = Wmo + (size_t)(R - 640) * DD;
            a_sm[idx] = A[j];
        }
        __syncthreads();
        const int col = t & 127, rr = t >> 7;
        float a0 = 0.f, a1 = 0.f, a2 = 0.f, a3 = 0.f;
        if (r0 < 640) {
            const float* Bm = (r0 < 384) ? Wmq : (r0 < 512) ? Wmk : Wmv;
#pragma unroll 8
            for (int j = 0; j < DD; j++) {
                float bv = Bm[j * DD + col];
                a0 = fmaf(a_sm[(rr + 0) * DD + j], bv, a0);
                a1 = fmaf(a_sm[(rr + 2) * DD + j], bv, a1);
                a2 = fmaf(a_sm[(rr + 4) * DD + j], bv, a2);
                a3 = fmaf(a_sm[(rr + 6) * DD + j], bv, a3);
            }
        } else {
            // ZW[m][i] = sum_j Wmo[m][j] * Wks[i][j]; col = i
#pragma unroll 4
            for (int j = 0; j < DD; j += 4) {
                float4 wv = *(const float4*)(Wks + (size_t)col * DD + j);
                a0 = fmaf(a_sm[(rr + 0) * DD + j],     wv.x, a0);
                a0 = fmaf(a_sm[(rr + 0) * DD + j + 1], wv.y, a0);
                a0 = fmaf(a_sm[(rr + 0) * DD + j + 2], wv.z, a0);
                a0 = fmaf(a_sm[(rr + 0) * DD + j + 3], wv.w, a0);
                a1 = fmaf(a_sm[(rr + 2) * DD + j],     wv.x, a1);
                a1 = fmaf(a_sm[(rr + 2) * DD + j + 1], wv.y, a1);
                a1 = fmaf(a_sm[(rr + 2) * DD + j + 2], wv.z, a1);
                a1 = fmaf(a_sm[(rr + 2) * DD + j + 3], wv.w, a1);
                a2 = fmaf(a_sm[(rr + 4) * DD + j],     wv.x, a2);
                a2 = fmaf(a_sm[(rr + 4) * DD + j + 1], wv.y, a2);
                a2 = fmaf(a_sm[(rr + 4) * DD + j + 2], wv.z, a2);
                a2 = fmaf(a_sm[(rr + 4) * DD + j + 3], wv.w, a2);
                a3 = fmaf(a_sm[(rr + 6) * DD + j],     wv.x, a3);
                a3 = fmaf(a_sm[(rr + 6) * DD + j + 1], wv.y, a3);
                a3 = fmaf(a_sm[(rr + 6) * DD + j + 2], wv.z, a3);
                a3 = fmaf(a_sm[(rr + 6) * DD + j + 3], wv.w, a3);
            }
        }
        if (r0 >= 384 && r0 < 512) {
            // Z region: store TRANSPOSED (Zt[k][i]); k = col, i = output row
            int ib = r0 - 384 + rr;
            float* zt = g_fold + (size_t)(384 + col) * DD;
            zt[ib + 0] = a0;
            zt[ib + 2] = a1;
            zt[ib + 4] = a2;
            zt[ib + 6] = a3;
        } else {
            g_fold[(size_t)(r0 + rr + 0) * DD + col] = a0;
            g_fold[(size_t)(r0 + rr + 2) * DD + col] = a1;
            g_fold[(size_t)(r0 + rr + 4) * DD + col] = a2;
            g_fold[(size_t)(r0 + rr + 6) * DD + col] = a3;
        }
        return;
    }

    // ---------------- means path ----------------
    const int bs = blockIdx.x - PRE_CTAS;
    const int b = bs / SPLIT;
    const int s = bs % SPLIT;

    const long long mbase = (long long)b * NN + s * CH;
    for (int n = t; n < CH; n += 256) {
        mloc[n]  = rdmask(maskp,  flag, mbase + n) ? 1 : 0;
        cmloc[n] = rdmask(cmaskp, flag, mbase + n) ? 1 : 0;
    }
    __syncthreads();

    const float* np_ = node + ((size_t)b * NN + (size_t)s * CH) * DD;
    const int d0 = lane * 4;
    float4 a1 = make_float4(0.f, 0.f, 0.f, 0.f);
    float4 a2 = make_float4(0.f, 0.f, 0.f, 0.f);
#pragma unroll 6
    for (int n = w; n < CH; n += 8) {
        float4 v = __ldcs((const float4*)(np_ + (size_t)n * DD + d0));
        bool m = mloc[n] != 0;
        bool mc = (mloc[n] | cmloc[n]) != 0;
        if (!m)  { a1.x += v.x; a1.y += v.y; a1.z += v.z; a1.w += v.w; }
        if (!mc) { a2.x += v.x; a2.y += v.y; a2.z += v.z; a2.w += v.w; }
    }
    int o = w * 128 + d0;
    red[o] = a1.x; red[o + 1] = a1.y; red[o + 2] = a1.z; red[o + 3] = a1.w;
    red[1024 + o] = a2.x; red[1024 + o + 1] = a2.y;
    red[1024 + o + 2] = a2.z; red[1024 + o + 3] = a2.w;
    __syncthreads();
    if (t < DD) {
        float s1 = 0.f, s2 = 0.f;
#pragma unroll
        for (int ww = 0; ww < 8; ww++) {
            s1 += red[ww * 128 + t];
            s2 += red[1024 + ww * 128 + t];
        }
        size_t idx = (size_t)(b * SPLIT + s) * DD + t;
        g_part[idx] = s1;
        g_part[G2OFF + idx] = s2;
    }
}

// ============================================================================
// Kernel 2: per-batch fused compute. Zt/ZV cp.async-staged, PQ/ZW register
// prefetched. grid = B, block = 512.
// ============================================================================
__global__ void __launch_bounds__(512, 1)
clu_fused_kernel(const float* __restrict__ depot, const float* __restrict__ cluster,
                 const float* __restrict__ curE,
                 const void* __restrict__ isnewp,
                 const void* __restrict__ vcmp, const void* __restrict__ maskp,
                 float* __restrict__ out) {
    extern __shared__ float sm[];
    const int b = blockIdx.x;
    const int t = threadIdx.x;
    const int lane = t & 31;
    const int w = t >> 5;
    const int c4 = lane * 4;

    // sniff bool dtype
    unsigned wword = ((const unsigned*)maskp)[t];
    int o1  = __syncthreads_or((wword & 0x0000ff00u) ? 1 : 0);
    int o23 = __syncthreads_or((wword & 0xffff0000u) ? 1 : 0);
    const int flag = o1 ? 0 : (o23 ? 2 : 1);
    const bool isnew = rdmask(isnewp, flag, b);

    // ===== P0: cp.async Zt/ZV, loads, means reduce, ctx build ===============
    {
        uint32_t sbase = (uint32_t)__cvta_generic_to_shared(sm);
        const char* gZt = (const char*)(g_fold + 384 * DD);
        const char* gZv = (const char*)(g_fold + 512 * DD);
#pragma unroll
        for (int j = 0; j < 8; j++) {
            int idx = t + 512 * j;
            cpasync16(sbase + S_ZT * 4 + idx * 16, gZt + idx * 16);
        }
        CP_COMMIT();
#pragma unroll
        for (int j = 0; j < 8; j++) {
            int idx = t + 512 * j;
            cpasync16(sbase + S_ZV * 4 + idx * 16, gZv + idx * 16);
        }
        CP_COMMIT();
    }
    if (t < DD) {
        sm[S_CUR + t] = curE[b * DD + t];
        sm[S_DEP + t] = depot[b * DD + t];
    }
    if (t < CC) sm[S_VCM + t] = rdmask(vcmp, flag, (long long)b * CC + t) ? 1.0f : 0.0f;
    {
        const float* cp = cluster + (size_t)b * CC * DD;
        for (int p4 = t; p4 < (CC * DD) / 4; p4 += 512) {
            float4 v = ((const float4*)cp)[p4];
            int base = p4 * 4;
            float* dst = sm + S_CS + (base >> 7) * 129 + (base & 127);
            dst[0] = v.x; dst[1] = v.y; dst[2] = v.z; dst[3] = v.w;
        }
    }
    if (t < DD) {
        float s1 = 0.f, s2 = 0.f;
#pragma unroll
        for (int s = 0; s < SPLIT; s++) {
            size_t idx = (size_t)(b * SPLIT + s) * DD + t;
            s1 += g_part[idx];
            s2 += g_part[G2OFF + idx];
        }
        float m1 = s1 * (1.0f / NN);
        sm[S_M1 + t] = m1;
        sm[S_M2 + t] = s2 * (1.0f / NN);
        sm[S_CTX + t] = m1;
        sm[S_CTX + 128 + t] = sm[S_CUR + t];
        sm[S_CTX + 256 + t] = sm[S_DEP + t];
    }
    __syncthreads();

    // ===== P1: qh partials — warp w: 24 PQ rows, register double-buffered ===
    {
        const float* PQ = g_fold;
        const int r0 = w * 24;
        float4 pa[8], pb[8];
#pragma unroll
        for (int j = 0; j < 8; j++)
            pa[j] = __ldg((const float4*)(PQ + (size_t)(r0 + j) * DD + c4));
#pragma unroll
        for (int j = 0; j < 8; j++)
            pb[j] = __ldg((const float4*)(PQ + (size_t)(r0 + 8 + j) * DD + c4));
        float4 acc = make_float4(0.f, 0.f, 0.f, 0.f);
#pragma unroll
        for (int j = 0; j < 8; j++) {
            float cx = sm[S_CTX + r0 + j];
            acc.x = fmaf(cx, pa[j].x, acc.x);
            acc.y = fmaf(cx, pa[j].y, acc.y);
            acc.z = fmaf(cx, pa[j].z, acc.z);
            acc.w = fmaf(cx, pa[j].w, acc.w);
        }
#pragma unroll
        for (int j = 0; j < 8; j++)
            pa[j] = __ldg((const float4*)(PQ + (size_t)(r0 + 16 + j) * DD + c4));
#pragma unroll
        for (int j = 0; j < 8; j++) {
            float cx = sm[S_CTX + r0 + 8 + j];
            acc.x = fmaf(cx, pb[j].x, acc.x);
            acc.y = fmaf(cx, pb[j].y, acc.y);
            acc.z = fmaf(cx, pb[j].z, acc.z);
            acc.w = fmaf(cx, pb[j].w, acc.w);
        }
#pragma unroll
        for (int j = 0; j < 8; j++) {
            float cx = sm[S_CTX + r0 + 16 + j];
            acc.x = fmaf(cx, pa[j].x, acc.x);
            acc.y = fmaf(cx, pa[j].y, acc.y);
            acc.z = fmaf(cx, pa[j].z, acc.z);
            acc.w = fmaf(cx, pa[j].w, acc.w);
        }
        *(float4*)(sm + S_PB + w * 132 + c4) = acc;
        if (w == 15) {  // vcm[0] adjustment
            bool ok = true;
            for (int c = 1 + lane; c < CC; c += 32) ok = ok && (sm[S_VCM + c] != 0.0f);
            bool allv = __all_sync(0xffffffffu, ok);
            if (lane == 0 && isnew) sm[S_VCM + 0] = allv ? 0.0f : 1.0f;
        }
    }
    __syncthreads();

    // ===== P2: qh reduce  (+ ensure Zt staged) ===============================
    if (t < DD) {
        float s = 0.f;
#pragma unroll
        for (int ww = 0; ww < 16; ww++) s += sm[S_PB + ww * 132 + t];
        sm[S_QH + t] = s;
    }
    CP_WAIT(1);   // Zt group complete (all threads)
    __syncthreads();

    // ===== P3: u[i][h] — warp w (<8) = head w, 16 rows of smem Zt ============
    if (w < 8) {
        float4 acc = make_float4(0.f, 0.f, 0.f, 0.f);
#pragma unroll
        for (int k = 0; k < 16; k++) {
            float4 zv = *(const float4*)(sm + S_ZT + (16 * w + k) * 128 + c4);
            float q = sm[S_QH + 16 * w + k];
            acc.x = fmaf(q, zv.x, acc.x);
            acc.y = fmaf(q, zv.y, acc.y);
            acc.z = fmaf(q, zv.z, acc.z);
            acc.w = fmaf(q, zv.w, acc.w);
        }
        sm[S_U4 + (c4 + 0) * 8 + w] = acc.x;
        sm[S_U4 + (c4 + 1) * 8 + w] = acc.y;
        sm[S_U4 + (c4 + 2) * 8 + w] = acc.z;
        sm[S_U4 + (c4 + 3) * 8 + w] = acc.w;
    }
    __syncthreads();

    // ===== P4: score partials — 400 threads: c = t>>2, quarter q = t&3 ======
    if (t < 4 * CC) {
        int c = t >> 2, q = t & 3;
        int base = q * 32;
        float acc[8] = {0.f, 0.f, 0.f, 0.f, 0.f, 0.f, 0.f, 0.f};
#pragma unroll 4
        for (int kk = 0; kk < 32; kk++) {
            int i = base + ((kk + 8 * q) & 31);   // bank stagger
            float cv = sm[S_CS + c * 129 + i];
            float4 u0 = *(const float4*)(sm + S_U4 + i * 8);
            float4 u1 = *(const float4*)(sm + S_U4 + i * 8 + 4);
            acc[0] = fmaf(cv, u0.x, acc[0]);
            acc[1] = fmaf(cv, u0.y, acc[1]);
            acc[2] = fmaf(cv, u0.z, acc[2]);
            acc[3] = fmaf(cv, u0.w, acc[3]);
            acc[4] = fmaf(cv, u1.x, acc[4]);
            acc[5] = fmaf(cv, u1.y, acc[5]);
            acc[6] = fmaf(cv, u1.z, acc[6]);
            acc[7] = fmaf(cv, u1.w, acc[7]);
        }
#pragma unroll
        for (int h = 0; h < HH; h++) sm[S_SCP + c * 33 + q * 8 + h] = acc[h];
    }
    __syncthreads();

    // ===== P5: softmax — warp w (<8) handles head h=w ========================
    if (w < 8) {
        int h = w;
        float vv[4];
        float mx = -INFINITY;
#pragma unroll
        for (int idx = 0; idx < 4; idx++) {
            int c = lane + 32 * idx;
            float val = -INFINITY;
            if (c < CC) {
                float scv = sm[S_SCP + c * 33 + h]      + sm[S_SCP + c * 33 + 8 + h]
                          + sm[S_SCP + c * 33 + 16 + h] + sm[S_SCP + c * 33 + 24 + h];
                val = (sm[S_VCM + c] != 0.0f) ? NEGV : scv * 0.25f;
            }
            vv[idx] = val;
            mx = fmaxf(mx, val);
        }
#pragma unroll
        for (int off = 16; off; off >>= 1)
            mx = fmaxf(mx, __shfl_xor_sync(0xffffffffu, mx, off));
        float ssum = 0.f;
#pragma unroll
        for (int idx = 0; idx < 4; idx++) {
            int c = lane + 32 * idx;
            if (c < CC) {
                float e = __expf(vv[idx] - mx);
                ssum += e;
                vv[idx] = e;
            }
        }
#pragma unroll
        for (int off = 16; off; off >>= 1)
            ssum += __shfl_xor_sync(0xffffffffu, ssum, off);
        float inv = 1.0f / ssum;
#pragma unroll
        for (int idx = 0; idx < 4; idx++) {
            int c = lane + 32 * idx;
            if (c < CC) sm[S_AT4 + c * 8 + h] = vv[idx] * inv;
        }
    }
    __syncthreads();

    // ===== P6: wsum[h][i] = sum_c attn[h][c]*cluster[c][i] (t<256) ===========
    if (t < 256) {
        int i = t & 127, par = t >> 7;
        float acc[4] = {0.f, 0.f, 0.f, 0.f};
#pragma unroll 4
        for (int c = 0; c < CC; c++) {
            float cv = sm[S_CS + c * 129 + i];
            float4 av = *(const float4*)(sm + S_AT4 + c * 8 + par * 4);
            acc[0] = fmaf(av.x, cv, acc[0]);
            acc[1] = fmaf(av.y, cv, acc[1]);
            acc[2] = fmaf(av.z, cv, acc[2]);
            acc[3] = fmaf(av.w, cv, acc[3]);
        }
        *(float4*)(sm + S_WS4 + i * 8 + par * 4) =
            make_float4(acc[0], acc[1], acc[2], acc[3]);
    }
    CP_WAIT(0);   // ZV group complete (all threads)
    __syncthreads();

    // ===== P7: prefetch ZW to regs; gv partials from smem ZV =================
    float4 zw[8];
    {
        const float* ZW = g_fold + 640 * DD;
#pragma unroll
        for (int mm = 0; mm < 8; mm++)
            zw[mm] = __ldg((const float4*)(ZW + (size_t)(w * 8 + mm) * DD + c4));
        const int hsel = lane >> 2;
        float4 acc = make_float4(0.f, 0.f, 0.f, 0.f);
#pragma unroll
        for (int ii = 0; ii < 8; ii++) {
            int i = w * 8 + ii;
            float4 zv = *(const float4*)(sm + S_ZV + i * 128 + c4);
            float s = sm[S_WS4 + i * 8 + hsel];
            acc.x = fmaf(s, zv.x, acc.x);
            acc.y = fmaf(s, zv.y, acc.y);
            acc.z = fmaf(s, zv.z, acc.z);
            acc.w = fmaf(s, zv.w, acc.w);
        }
        *(float4*)(sm + S_PB + w * 132 + c4) = acc;
    }
    __syncthreads();

    // ===== P8: gv reduce =====================================================
    if (t < DD) {
        float s = 0.f;
#pragma unroll
        for (int ww = 0; ww < 16; ww++) s += sm[S_PB + ww * 132 + t];
        sm[S_GV + t] = s;
    }
    __syncthreads();

    // ===== P9: gw partials — warp w: 8 rows of ZW from registers =============
    {
        float4 acc = make_float4(0.f, 0.f, 0.f, 0.f);
#pragma unroll
        for (int mm = 0; mm < 8; mm++) {
            float s = sm[S_GV + w * 8 + mm];
            acc.x = fmaf(s, zw[mm].x, acc.x);
            acc.y = fmaf(s, zw[mm].y, acc.y);
            acc.z = fmaf(s, zw[mm].z, acc.z);
            acc.w = fmaf(s, zw[mm].w, acc.w);
        }
        *(float4*)(sm + S_PB + w * 132 + c4) = acc;
    }
    __syncthreads();

    // ===== P10: gw reduce ====================================================
    if (t < DD) {
        float s = 0.f;
#pragma unroll
        for (int ww = 0; ww < 16; ww++) s += sm[S_PB + ww * 132 + t];
        sm[S_GW + t] = s;
    }
    __syncthreads();

    // ===== P11: logit partials (t<200) =======================================
    if (t < 2 * CC) {
        int c = t >> 1, half = t & 1;
        float acc = 0.f;
        int i0 = half * 64;
#pragma unroll 8
        for (int i = i0; i < i0 + 64; i++)
            acc = fmaf(sm[S_CS + c * 129 + i], sm[S_GW + i], acc);
        sm[S_PART + c * 2 + half] = acc;
    }
    __syncthreads();

    // ===== P12: finalize logits + argmax + lse (warp 0) ======================
    if (w == 0) {
        float vv[4];
        float bv = -INFINITY;
        int bi = 0x7fffffff;
#pragma unroll
        for (int idx = 0; idx < 4; idx++) {
            int c = lane + 32 * idx;
            float val = -INFINITY;
            if (c < CC) {
                float lg = (sm[S_PART + c * 2] + sm[S_PART + c * 2 + 1])
                           * 0.08838834764831845f;
                lg = tanhf(lg) * CLIPV;
                val = (sm[S_VCM + c] != 0.0f) ? NEGV : lg;
                sm[S_LGT + c] = val;
                if (val > bv || (val == bv && c < bi)) { bv = val; bi = c; }
            }
            vv[idx] = val;
        }
#pragma unroll
        for (int off = 16; off; off >>= 1) {
            float ov = __shfl_down_sync(0xffffffffu, bv, off);
            int oi = __shfl_down_sync(0xffffffffu, bi, off);
            if (ov > bv || (ov == bv && oi < bi)) { bv = ov; bi = oi; }
        }
        bv = __shfl_sync(0xffffffffu, bv, 0);
        bi = __shfl_sync(0xffffffffu, bi, 0);
        float s = 0.f;
#pragma unroll
        for (int idx = 0; idx < 4; idx++) {
            int c = lane + 32 * idx;
            if (c < CC) s += __expf(vv[idx] - bv);
        }
#pragma unroll
        for (int off = 16; off; off >>= 1) s += __shfl_xor_sync(0xffffffffu, s, off);
        if (lane == 0) {
            sm[S_MISC + 0] = (float)bi;
            sm[S_MISC + 1] = bv + __logf(s);
        }
    }
    __syncthreads();

    // ===== P13: outputs ======================================================
    const int gid = (int)sm[S_MISC + 0];
    const float mlse = sm[S_MISC + 1];
    float* aug = out + OUT_AUG + (size_t)b * 512;
    float* gout = out + OUT_GEMB + (size_t)b * 128;
    float* cpo = out + OUT_CLU + (size_t)b * CC;
    if (t < DD) {
        float ge = sm[S_CS + gid * 129 + t];
        aug[t]        = isnew ? sm[S_M2 + t] : 0.0f;
        aug[128 + t]  = isnew ? sm[S_CUR + t] : 0.0f;
        aug[256 + t]  = isnew ? ge : 0.0f;
        aug[384 + t]  = isnew ? sm[S_DEP + t] : 0.0f;
        gout[t]       = isnew ? ge : 0.0f;
    }
    if (t >= 256 && t < 256 + CC) {
        int c = t - 256;
        cpo[c] = isnew ? (sm[S_LGT + c] - mlse) : 0.0f;
    }
    if (t == 511) out[OUT_GUID + b] = isnew ? (float)gid : 0.0f;
}

extern "C" void kernel_launch(void* const* d_in, const int* in_sizes, int n_in,
                              void* d_out, int out_size) {
    (void)in_sizes; (void)n_in; (void)out_size;
    const float* depot   = (const float*)d_in[0];
    const float* cluster = (const float*)d_in[1];
    const float* curE    = (const float*)d_in[2];
    const float* node    = (const float*)d_in[3];
    const void*  isnewp  = d_in[4];
    const void*  cmaskp  = d_in[5];
    const void*  vcmp    = d_in[6];
    const void*  maskp   = d_in[7];
    const float* Wq  = (const float*)d_in[8];
    const float* Wk  = (const float*)d_in[9];
    const float* Wv  = (const float*)d_in[10];
    const float* Wks = (const float*)d_in[11];
    const float* Wmq = (const float*)d_in[12];
    const float* Wmk = (const float*)d_in[13];
    const float* Wmv = (const float*)d_in[14];
    const float* Wmo = (const float*)d_in[15];

    means_pre_kernel<<<PRE_CTAS + BB * SPLIT, 256>>>(
        node, maskp, cmaskp, Wq, Wk, Wv, Wks, Wmq, Wmk, Wmv, Wmo);

    cudaFuncSetAttribute(clu_fused_kernel,
                         cudaFuncAttributeMaxDynamicSharedMemorySize, SMEM_BYTES);
    clu_fused_kernel<<<BB, 512, SMEM_BYTES>>>(
        depot, cluster, curE, isnewp, vcmp, maskp, (float*)d_out);
}

// round 13
// speedup vs baseline: 1.0878x; 1.0878x over previous
#include <cuda_runtime.h>
#include <math.h>

// Problem constants
#define BB 128
#define NN 2000
#define CC 100
#define DD 128
#define HH 8
#define NEGV (-1000000000.0f)
#define CLIPV 10.0f

#define SPLIT 20
#define CH (NN / SPLIT)       // 100 nodes per chunk
#define PRE_CTAS 96           // weight-folding CTAs (placed first in grid)
#define FOLD_ROWS 768         // PQ:0..383  Zt:384..511  ZV:512..639  ZW:640..767

// Output layout (float32, flattened tuple order)
#define OUT_AUG 0
#define OUT_GEMB 65536
#define OUT_GUID 81920
#define OUT_CLU 82048

// Global scratch
#define G2OFF (BB * SPLIT * DD)
__device__ float g_part[2 * BB * SPLIT * DD];   // partial masked sums
__device__ float g_fold[FOLD_ROWS * DD];        // folded weight products

// ---------------- Kernel 2 shared memory layout (float offsets) -------------
#define S_CS   0        // cluster tile [100][129]
#define S_PB   12900    // warp partials A [16][132]
#define S_PB2  15012    // warp partials B [16][132]
#define S_ZVS  17124    // ZV staged [128*128]
#define S_ZWS  33508    // ZW staged [128*128]
#define S_M2   49892
#define S_CUR  50020
#define S_DEP  50148
#define S_CTX  50276    // [384]
#define S_U4   50660    // u packed [128][8]
#define S_SCP  51684    // score partials [100][16]
#define S_AT4  53284    // attn packed [100][8]
#define S_WS4  54084    // wsum packed [128][8]
#define S_GW   55108
#define S_PART 55236    // [100][2] + pad
#define S_LGT  55444
#define S_MISC 55548
#define S_VCM  55552
#define SMEM_FLOATS 55656
#define SMEM_BYTES (SMEM_FLOATS * 4)

__device__ __forceinline__ bool rdmask(const void* p, int flag, long long i) {
    if (flag == 0) return ((const unsigned char*)p)[i] != 0;
    if (flag == 1) return ((const int*)p)[i] != 0;
    return ((const float*)p)[i] != 0.0f;
}

// ============================================================================
// Kernel 1: [blocks 0..95] weight folding  +  [blocks 96..] masked partial
// sums over node_embeddings. grid = PRE_CTAS + B*SPLIT.  (unchanged from R11)
// ============================================================================
__global__ void __launch_bounds__(256)
means_pre_kernel(const float* __restrict__ node, const void* __restrict__ maskp,
                 const void* __restrict__ cmaskp,
                 const float* __restrict__ Wq, const float* __restrict__ Wk,
                 const float* __restrict__ Wv, const float* __restrict__ Wks,
                 const float* __restrict__ Wmq, const float* __restrict__ Wmk,
                 const float* __restrict__ Wmv, const float* __restrict__ Wmo) {
    __shared__ float red[2 * 1024];
    __shared__ float a_sm[8 * 128];
    __shared__ unsigned char mloc[CH], cmloc[CH];
    const int t = threadIdx.x;
    const int lane = t & 31;
    const int w = t >> 5;

    // sniff bool serialization dtype (byte / int32 / float32)
    unsigned wword = ((const unsigned*)maskp)[t];
    int o1  = __syncthreads_or((wword & 0x0000ff00u) ? 1 : 0);
    int o23 = __syncthreads_or((wword & 0xffff0000u) ? 1 : 0);
    const int flag = o1 ? 0 : (o23 ? 2 : 1);

    if (blockIdx.x < PRE_CTAS) {
        const int r0 = blockIdx.x * 8;
        for (int idx = t; idx < 8 * 128; idx += 256) {
            int row = idx >> 7, j = idx & 127;
            int R = r0 + row;
            const float* A;
            if (R < 384)      A = Wq  + (size_t)R * DD;
            else if (R < 512) A = Wk  + (size_t)(R - 384) * DD;
            else if (R < 640) A = Wv  + (size_t)(R - 512) * DD;
            else              A = Wmo + (size_t)(R - 640) * DD;
            a_sm[idx] = A[j];
        }
        __syncthreads();
        const int col = t & 127, rr = t >> 7;
        float a0 = 0.f, a1 = 0.f, a2 = 0.f, a3 = 0.f;
        if (r0 < 640) {
            const float* Bm = (r0 < 384) ? Wmq : (r0 < 512) ? Wmk : Wmv;
#pragma unroll 8
            for (int j = 0; j < DD; j++) {
                float bv = Bm[j * DD + col];
                a0 = fmaf(a_sm[(rr + 0) * DD + j], bv, a0);
                a1 = fmaf(a_sm[(rr + 2) * DD + j], bv, a1);
                a2 = fmaf(a_sm[(rr + 4) * DD + j], bv, a2);
                a3 = fmaf(a_sm[(rr + 6) * DD + j], bv, a3);
            }
        } else {
            // ZW[m][i] = sum_j Wmo[m][j] * Wks[i][j]; col = i
#pragma unroll 4
            for (int j = 0; j < DD; j += 4) {
                float4 wv = *(const float4*)(Wks + (size_t)col * DD + j);
                a0 = fmaf(a_sm[(rr + 0) * DD + j],     wv.x, a0);
                a0 = fmaf(a_sm[(rr + 0) * DD + j + 1], wv.y, a0);
                a0 = fmaf(a_sm[(rr + 0) * DD + j + 2], wv.z, a0);
                a0 = fmaf(a_sm[(rr + 0) * DD + j + 3], wv.w, a0);
                a1 = fmaf(a_sm[(rr + 2) * DD + j],     wv.x, a1);
                a1 = fmaf(a_sm[(rr + 2) * DD + j + 1], wv.y, a1);
                a1 = fmaf(a_sm[(rr + 2) * DD + j + 2], wv.z, a1);
                a1 = fmaf(a_sm[(rr + 2) * DD + j + 3], wv.w, a1);
                a2 = fmaf(a_sm[(rr + 4) * DD + j],     wv.x, a2);
                a2 = fmaf(a_sm[(rr + 4) * DD + j + 1], wv.y, a2);
                a2 = fmaf(a_sm[(rr + 4) * DD + j + 2], wv.z, a2);
                a2 = fmaf(a_sm[(rr + 4) * DD + j + 3], wv.w, a2);
                a3 = fmaf(a_sm[(rr + 6) * DD + j],     wv.x, a3);
                a3 = fmaf(a_sm[(rr + 6) * DD + j + 1], wv.y, a3);
                a3 = fmaf(a_sm[(rr + 6) * DD + j + 2], wv.z, a3);
                a3 = fmaf(a_sm[(rr + 6) * DD + j + 3], wv.w, a3);
            }
        }
        if (r0 >= 384 && r0 < 512) {
            // Z region: store TRANSPOSED (Zt[k][i]); k = col, i = output row
            int ib = r0 - 384 + rr;
            float* zt = g_fold + (size_t)(384 + col) * DD;
            zt[ib + 0] = a0;
            zt[ib + 2] = a1;
            zt[ib + 4] = a2;
            zt[ib + 6] = a3;
        } else {
            g_fold[(size_t)(r0 + rr + 0) * DD + col] = a0;
            g_fold[(size_t)(r0 + rr + 2) * DD + col] = a1;
            g_fold[(size_t)(r0 + rr + 4) * DD + col] = a2;
            g_fold[(size_t)(r0 + rr + 6) * DD + col] = a3;
        }
        return;
    }

    // ---------------- means path ----------------
    const int bs = blockIdx.x - PRE_CTAS;
    const int b = bs / SPLIT;
    const int s = bs % SPLIT;

    const long long mbase = (long long)b * NN + s * CH;
    for (int n = t; n < CH; n += 256) {
        mloc[n]  = rdmask(maskp,  flag, mbase + n) ? 1 : 0;
        cmloc[n] = rdmask(cmaskp, flag, mbase + n) ? 1 : 0;
    }
    __syncthreads();

    const float* np_ = node + ((size_t)b * NN + (size_t)s * CH) * DD;
    const int d0 = lane * 4;
    float4 a1 = make_float4(0.f, 0.f, 0.f, 0.f);
    float4 a2 = make_float4(0.f, 0.f, 0.f, 0.f);
#pragma unroll 6
    for (int n = w; n < CH; n += 8) {
        float4 v = __ldcs((const float4*)(np_ + (size_t)n * DD + d0));
        bool m = mloc[n] != 0;
        bool mc = (mloc[n] | cmloc[n]) != 0;
        if (!m)  { a1.x += v.x; a1.y += v.y; a1.z += v.z; a1.w += v.w; }
        if (!mc) { a2.x += v.x; a2.y += v.y; a2.z += v.z; a2.w += v.w; }
    }
    int o = w * 128 + d0;
    red[o] = a1.x; red[o + 1] = a1.y; red[o + 2] = a1.z; red[o + 3] = a1.w;
    red[1024 + o] = a2.x; red[1024 + o + 1] = a2.y;
    red[1024 + o + 2] = a2.z; red[1024 + o + 3] = a2.w;
    __syncthreads();
    if (t < DD) {
        float s1 = 0.f, s2 = 0.f;
#pragma unroll
        for (int ww = 0; ww < 8; ww++) {
            s1 += red[ww * 128 + t];
            s2 += red[1024 + ww * 128 + t];
        }
        size_t idx = (size_t)(b * SPLIT + s) * DD + t;
        g_part[idx] = s1;
        g_part[G2OFF + idx] = s2;
    }
}

// ============================================================================
// Kernel 2: per-batch fused compute. R11 base + idle-warp staging of ZV/ZW +
// warp-local QH/GV reductions. grid = B, block = 512.
// ============================================================================
__global__ void __launch_bounds__(512, 1)
clu_fused_kernel(const float* __restrict__ depot, const float* __restrict__ cluster,
                 const float* __restrict__ curE,
                 const void* __restrict__ isnewp,
                 const void* __restrict__ vcmp, const void* __restrict__ maskp,
                 float* __restrict__ out) {
    extern __shared__ float sm[];
    const int b = blockIdx.x;
    const int t = threadIdx.x;
    const int lane = t & 31;
    const int w = t >> 5;
    const int c4 = lane * 4;

    // sniff bool dtype
    unsigned wword = ((const unsigned*)maskp)[t];
    int o1  = __syncthreads_or((wword & 0x0000ff00u) ? 1 : 0);
    int o23 = __syncthreads_or((wword & 0xffff0000u) ? 1 : 0);
    const int flag = o1 ? 0 : (o23 ? 2 : 1);
    const bool isnew = rdmask(isnewp, flag, b);

    // ===== P0: means reduce (t<128 first), small loads, cluster tile ========
    if (t < DD) {
        float s1 = 0.f, s2 = 0.f;
#pragma unroll
        for (int s = 0; s < SPLIT; s++) {
            size_t idx = (size_t)(b * SPLIT + s) * DD + t;
            s1 += g_part[idx];
            s2 += g_part[G2OFF + idx];
        }
        float cu = curE[b * DD + t];
        float de = depot[b * DD + t];
        sm[S_CUR + t] = cu;
        sm[S_DEP + t] = de;
        sm[S_M2 + t] = s2 * (1.0f / NN);
        sm[S_CTX + t] = s1 * (1.0f / NN);
        sm[S_CTX + 128 + t] = cu;
        sm[S_CTX + 256 + t] = de;
    }
    if (t < CC) sm[S_VCM + t] = rdmask(vcmp, flag, (long long)b * CC + t) ? 1.0f : 0.0f;
    {
        const float* cp = cluster + (size_t)b * CC * DD;
        for (int p4 = t; p4 < (CC * DD) / 4; p4 += 512) {
            float4 v = ((const float4*)cp)[p4];
            int base = p4 * 4;
            float* dst = sm + S_CS + (base >> 7) * 129 + (base & 127);
            dst[0] = v.x; dst[1] = v.y; dst[2] = v.z; dst[3] = v.w;
        }
    }
    __syncthreads();

    // ===== P1: qh partials — warp w takes 24 rows of PQ =====================
    {
        float4 acc = make_float4(0.f, 0.f, 0.f, 0.f);
        int r0 = w * 24;
#pragma unroll 6
        for (int r = r0; r < r0 + 24; r++) {
            float4 pv = *(const float4*)(g_fold + (size_t)r * DD + c4);
            float cx = sm[S_CTX + r];
            acc.x = fmaf(cx, pv.x, acc.x);
            acc.y = fmaf(cx, pv.y, acc.y);
            acc.z = fmaf(cx, pv.z, acc.z);
            acc.w = fmaf(cx, pv.w, acc.w);
        }
        *(float4*)(sm + S_PB + w * 132 + c4) = acc;
        if (w == 15) {  // vcm[0] adjustment
            bool ok = true;
            for (int c = 1 + lane; c < CC; c += 32) ok = ok && (sm[S_VCM + c] != 0.0f);
            bool allv = __all_sync(0xffffffffu, ok);
            if (lane == 0 && isnew) sm[S_VCM + 0] = allv ? 0.0f : 1.0f;
        }
    }
    __syncthreads();

    // ===== P3: warps 0-7: warp-local QH reduce + u[i][h] from Zt (L2) =======
    //          warps 8-15: stage ZV -> smem
    if (w < 8) {
        // QH[16w + (lane&15)] reduced from partial buffer (order ww=0..15)
        const int qidx = 16 * w + (lane & 15);
        float qh_l = 0.f;
#pragma unroll
        for (int ww = 0; ww < 16; ww++) qh_l += sm[S_PB + ww * 132 + qidx];

        const float* Zt = g_fold + 384 * DD;
        float4 acc = make_float4(0.f, 0.f, 0.f, 0.f);
#pragma unroll
        for (int k = 0; k < 16; k++) {
            float q = __shfl_sync(0xffffffffu, qh_l, k);
            float4 zv = *(const float4*)(Zt + (size_t)(16 * w + k) * DD + c4);
            acc.x = fmaf(q, zv.x, acc.x);
            acc.y = fmaf(q, zv.y, acc.y);
            acc.z = fmaf(q, zv.z, acc.z);
            acc.w = fmaf(q, zv.w, acc.w);
        }
        sm[S_U4 + (c4 + 0) * 8 + w] = acc.x;
        sm[S_U4 + (c4 + 1) * 8 + w] = acc.y;
        sm[S_U4 + (c4 + 2) * 8 + w] = acc.z;
        sm[S_U4 + (c4 + 3) * 8 + w] = acc.w;
    } else {
        const float4* gZV = (const float4*)(g_fold + 512 * DD);
        float4* sZV = (float4*)(sm + S_ZVS);
        const int u = t - 256;
#pragma unroll
        for (int j = 0; j < 16; j++) sZV[u + 256 * j] = gZV[u + 256 * j];
    }
    __syncthreads();

    // ===== P4: score partials (t<200: c, half)  ||  warps 8-15 stage ZW =====
    if (t < 2 * CC) {
        int c = t >> 1, half = t & 1, i0 = half * 64;
        float acc[8] = {0.f, 0.f, 0.f, 0.f, 0.f, 0.f, 0.f, 0.f};
#pragma unroll 4
        for (int i = i0; i < i0 + 64; i++) {
            float cv = sm[S_CS + c * 129 + i];
            float4 u0 = *(const float4*)(sm + S_U4 + i * 8);
            float4 u1 = *(const float4*)(sm + S_U4 + i * 8 + 4);
            acc[0] = fmaf(cv, u0.x, acc[0]);
            acc[1] = fmaf(cv, u0.y, acc[1]);
            acc[2] = fmaf(cv, u0.z, acc[2]);
            acc[3] = fmaf(cv, u0.w, acc[3]);
            acc[4] = fmaf(cv, u1.x, acc[4]);
            acc[5] = fmaf(cv, u1.y, acc[5]);
            acc[6] = fmaf(cv, u1.z, acc[6]);
            acc[7] = fmaf(cv, u1.w, acc[7]);
        }
#pragma unroll
        for (int h = 0; h < HH; h++) sm[S_SCP + c * 16 + half * 8 + h] = acc[h];
    } else if (t >= 256) {
        const float4* gZW = (const float4*)(g_fold + 640 * DD);
        float4* sZW = (float4*)(sm + S_ZWS);
        const int u = t - 256;
#pragma unroll
        for (int j = 0; j < 16; j++) sZW[u + 256 * j] = gZW[u + 256 * j];
    }
    __syncthreads();

    // ===== P5: softmax — warp w (<8) handles head h=w ========================
    if (w < 8) {
        int h = w;
        float vv[4];
        float mx = -INFINITY;
#pragma unroll
        for (int idx = 0; idx < 4; idx++) {
            int c = lane + 32 * idx;
            float val = -INFINITY;
            if (c < CC) {
                float scv = sm[S_SCP + c * 16 + h] + sm[S_SCP + c * 16 + 8 + h];
                val = (sm[S_VCM + c] != 0.0f) ? NEGV : scv * 0.25f;
            }
            vv[idx] = val;
            mx = fmaxf(mx, val);
        }
#pragma unroll
        for (int off = 16; off; off >>= 1)
            mx = fmaxf(mx, __shfl_xor_sync(0xffffffffu, mx, off));
        float ssum = 0.f;
#pragma unroll
        for (int idx = 0; idx < 4; idx++) {
            int c = lane + 32 * idx;
            if (c < CC) {
                float e = expf(vv[idx] - mx);
                ssum += e;
                vv[idx] = e;
            }
        }
#pragma unroll
        for (int off = 16; off; off >>= 1)
            ssum += __shfl_xor_sync(0xffffffffu, ssum, off);
        float inv = 1.0f / ssum;
#pragma unroll
        for (int idx = 0; idx < 4; idx++) {
            int c = lane + 32 * idx;
            if (c < CC) sm[S_AT4 + c * 8 + h] = vv[idx] * inv;
        }
    }
    __syncthreads();

    // ===== P6: wsum[h][i] = sum_c attn[h][c]*cluster[c][i] (t<256) ===========
    if (t < 256) {
        int i = t & 127, par = t >> 7;
        float acc[4] = {0.f, 0.f, 0.f, 0.f};
#pragma unroll 4
        for (int c = 0; c < CC; c++) {
            float cv = sm[S_CS + c * 129 + i];
            float4 av = *(const float4*)(sm + S_AT4 + c * 8 + par * 4);
            acc[0] = fmaf(av.x, cv, acc[0]);
            acc[1] = fmaf(av.y, cv, acc[1]);
            acc[2] = fmaf(av.z, cv, acc[2]);
            acc[3] = fmaf(av.w, cv, acc[3]);
        }
        *(float4*)(sm + S_WS4 + i * 8 + par * 4) =
            make_float4(acc[0], acc[1], acc[2], acc[3]);
    }
    __syncthreads();

    // ===== P7: gv partials — warp w takes 8 rows of smem ZV ==================
    {
        const int hsel = lane >> 2;
        float4 acc = make_float4(0.f, 0.f, 0.f, 0.f);
#pragma unroll
        for (int ii = 0; ii < 8; ii++) {
            int i = w * 8 + ii;
            float4 zv = *(const float4*)(sm + S_ZVS + i * 128 + c4);
            float s = sm[S_WS4 + i * 8 + hsel];
            acc.x = fmaf(s, zv.x, acc.x);
            acc.y = fmaf(s, zv.y, acc.y);
            acc.z = fmaf(s, zv.z, acc.z);
            acc.w = fmaf(s, zv.w, acc.w);
        }
        *(float4*)(sm + S_PB + w * 132 + c4) = acc;
    }
    __syncthreads();

    // ===== P9: warp-local GV reduce + gw partials from smem ZW ===============
    {
        // GV[8w + (lane&7)] reduced from partial buffer (order ww=0..15)
        const int gidx = 8 * w + (lane & 7);
        float gv_l = 0.f;
#pragma unroll
        for (int ww = 0; ww < 16; ww++) gv_l += sm[S_PB + ww * 132 + gidx];

        float4 acc = make_float4(0.f, 0.f, 0.f, 0.f);
#pragma unroll
        for (int mm = 0; mm < 8; mm++) {
            float s = __shfl_sync(0xffffffffu, gv_l, mm);
            float4 zw = *(const float4*)(sm + S_ZWS + (w * 8 + mm) * 128 + c4);
            acc.x = fmaf(s, zw.x, acc.x);
            acc.y = fmaf(s, zw.y, acc.y);
            acc.z = fmaf(s, zw.z, acc.z);
            acc.w = fmaf(s, zw.w, acc.w);
        }
        *(float4*)(sm + S_PB2 + w * 132 + c4) = acc;
    }
    __syncthreads();

    // ===== P10: gw reduce ====================================================
    if (t < DD) {
        float s = 0.f;
#pragma unroll
        for (int ww = 0; ww < 16; ww++) s += sm[S_PB2 + ww * 132 + t];
        sm[S_GW + t] = s;
    }
    __syncthreads();

    // ===== P11: logit partials (t<200) =======================================
    if (t < 2 * CC) {
        int c = t >> 1, half = t & 1;
        float acc = 0.f;
        int i0 = half * 64;
#pragma unroll 8
        for (int i = i0; i < i0 + 64; i++)
            acc = fmaf(sm[S_CS + c * 129 + i], sm[S_GW + i], acc);
        sm[S_PART + c * 2 + half] = acc;
    }
    __syncthreads();

    // ===== P12: finalize logits + argmax + lse (warp 0) ======================
    if (w == 0) {
        float vv[4];
        float bv = -INFINITY;
        int bi = 0x7fffffff;
#pragma unroll
        for (int idx = 0; idx < 4; idx++) {
            int c = lane + 32 * idx;
            float val = -INFINITY;
            if (c < CC) {
                float lg = (sm[S_PART + c * 2] + sm[S_PART + c * 2 + 1])
                           * 0.08838834764831845f;
                lg = tanhf(lg) * CLIPV;
                val = (sm[S_VCM + c] != 0.0f) ? NEGV : lg;
                sm[S_LGT + c] = val;
                if (val > bv || (val == bv && c < bi)) { bv = val; bi = c; }
            }
            vv[idx] = val;
        }
#pragma unroll
        for (int off = 16; off; off >>= 1) {
            float ov = __shfl_down_sync(0xffffffffu, bv, off);
            int oi = __shfl_down_sync(0xffffffffu, bi, off);
            if (ov > bv || (ov == bv && oi < bi)) { bv = ov; bi = oi; }
        }
        bv = __shfl_sync(0xffffffffu, bv, 0);
        bi = __shfl_sync(0xffffffffu, bi, 0);
        float s = 0.f;
#pragma unroll
        for (int idx = 0; idx < 4; idx++) {
            int c = lane + 32 * idx;
            if (c < CC) s += expf(vv[idx] - bv);
        }
#pragma unroll
        for (int off = 16; off; off >>= 1) s += __shfl_xor_sync(0xffffffffu, s, off);
        if (lane == 0) {
            sm[S_MISC + 0] = (float)bi;
            sm[S_MISC + 1] = bv + logf(s);
        }
    }
    __syncthreads();

    // ===== P13: outputs ======================================================
    const int gid = (int)sm[S_MISC + 0];
    const float mlse = sm[S_MISC + 1];
    float* aug = out + OUT_AUG + (size_t)b * 512;
    float* gout = out + OUT_GEMB + (size_t)b * 128;
    float* cpo = out + OUT_CLU + (size_t)b * CC;
    if (t < DD) {
        float ge = sm[S_CS + gid * 129 + t];
        aug[t]        = isnew ? sm[S_M2 + t] : 0.0f;
        aug[128 + t]  = isnew ? sm[S_CUR + t] : 0.0f;
        aug[256 + t]  = isnew ? ge : 0.0f;
        aug[384 + t]  = isnew ? sm[S_DEP + t] : 0.0f;
        gout[t]       = isnew ? ge : 0.0f;
    }
    if (t >= 256 && t < 256 + CC) {
        int c = t - 256;
        cpo[c] = isnew ? (sm[S_LGT + c] - mlse) : 0.0f;
    }
    if (t == 511) out[OUT_GUID + b] = isnew ? (float)gid : 0.0f;
}

extern "C" void kernel_launch(void* const* d_in, const int* in_sizes, int n_in,
                              void* d_out, int out_size) {
    (void)in_sizes; (void)n_in; (void)out_size;
    const float* depot   = (const float*)d_in[0];
    const float* cluster = (const float*)d_in[1];
    const float* curE    = (const float*)d_in[2];
    const float* node    = (const float*)d_in[3];
    const void*  isnewp  = d_in[4];
    const void*  cmaskp  = d_in[5];
    const void*  vcmp    = d_in[6];
    const void*  maskp   = d_in[7];
    const float* Wq  = (const float*)d_in[8];
    const float* Wk  = (const float*)d_in[9];
    const float* Wv  = (const float*)d_in[10];
    const float* Wks = (const float*)d_in[11];
    const float* Wmq = (const float*)d_in[12];
    const float* Wmk = (const float*)d_in[13];
    const float* Wmv = (const float*)d_in[14];
    const float* Wmo = (const float*)d_in[15];

    means_pre_kernel<<<PRE_CTAS + BB * SPLIT, 256>>>(
        node, maskp, cmaskp, Wq, Wk, Wv, Wks, Wmq, Wmk, Wmv, Wmo);

    cudaFuncSetAttribute(clu_fused_kernel,
                         cudaFuncAttributeMaxDynamicSharedMemorySize, SMEM_BYTES);
    clu_fused_kernel<<<BB, 512, SMEM_BYTES>>>(
        depot, cluster, curE, isnewp, vcmp, maskp, (float*)d_out);
}

// round 14
// speedup vs baseline: 1.0974x; 1.0089x over previous
#include <cuda_runtime.h>
#include <math.h>

// Problem constants
#define BB 128
#define NN 2000
#define CC 100
#define DD 128
#define HH 8
#define NEGV (-1000000000.0f)
#define CLIPV 10.0f

#define SPLIT 20
#define CH (NN / SPLIT)       // 100 nodes per chunk
#define PRE_CTAS 96           // weight-folding CTAs (placed first in grid)
#define FOLD_ROWS 768         // PQ:0..383  Zt:384..511  ZV:512..639  ZW:640..767

// Output layout (float32, flattened tuple order)
#define OUT_AUG 0
#define OUT_GEMB 65536
#define OUT_GUID 81920
#define OUT_CLU 82048

// Global scratch
#define G2OFF (BB * SPLIT * DD)
__device__ float g_part[2 * BB * SPLIT * DD];   // partial masked sums
__device__ float g_fold[FOLD_ROWS * DD];        // folded weight products

// ---------------- Kernel 2 shared memory layout (float offsets) -------------
#define S_CS   0        // cluster tile [100][129]
#define S_PB   12900    // warp partials A [16][132]
#define S_PB2  15012    // warp partials B [16][132]
#define S_M2   17124
#define S_CUR  17252
#define S_DEP  17380
#define S_CTX  17508    // [384]
#define S_U4   17892    // u packed [128][8]
#define S_SCP  18916    // score partials [100][16]
#define S_AT4  20516    // attn packed [100][8]
#define S_WS4  21316    // wsum packed [128][8]
#define S_GW   22340
#define S_PART 22468    // [100][2] + pad
#define S_LGT  22676
#define S_MISC 22780
#define S_VCM  22782
#define SMEM_FLOATS 22886
#define SMEM_BYTES (SMEM_FLOATS * 4)

__device__ __forceinline__ bool rdmask(const void* p, int flag, long long i) {
    if (flag == 0) return ((const unsigned char*)p)[i] != 0;
    if (flag == 1) return ((const int*)p)[i] != 0;
    return ((const float*)p)[i] != 0.0f;
}

// ============================================================================
// Kernel 1: [blocks 0..95] weight folding  +  [blocks 96..] masked partial
// sums over node_embeddings. grid = PRE_CTAS + B*SPLIT.  (unchanged from R11)
// ============================================================================
__global__ void __launch_bounds__(256)
means_pre_kernel(const float* __restrict__ node, const void* __restrict__ maskp,
                 const void* __restrict__ cmaskp,
                 const float* __restrict__ Wq, const float* __restrict__ Wk,
                 const float* __restrict__ Wv, const float* __restrict__ Wks,
                 const float* __restrict__ Wmq, const float* __restrict__ Wmk,
                 const float* __restrict__ Wmv, const float* __restrict__ Wmo) {
    __shared__ float red[2 * 1024];
    __shared__ float a_sm[8 * 128];
    __shared__ unsigned char mloc[CH], cmloc[CH];
    const int t = threadIdx.x;
    const int lane = t & 31;
    const int w = t >> 5;

    // sniff bool serialization dtype (byte / int32 / float32)
    unsigned wword = ((const unsigned*)maskp)[t];
    int o1  = __syncthreads_or((wword & 0x0000ff00u) ? 1 : 0);
    int o23 = __syncthreads_or((wword & 0xffff0000u) ? 1 : 0);
    const int flag = o1 ? 0 : (o23 ? 2 : 1);

    if (blockIdx.x < PRE_CTAS) {
        const int r0 = blockIdx.x * 8;
        for (int idx = t; idx < 8 * 128; idx += 256) {
            int row = idx >> 7, j = idx & 127;
            int R = r0 + row;
            const float* A;
            if (R < 384)      A = Wq  + (size_t)R * DD;
            else if (R < 512) A = Wk  + (size_t)(R - 384) * DD;
            else if (R < 640) A = Wv  + (size_t)(R - 512) * DD;
            else              A = Wmo + (size_t)(R - 640) * DD;
            a_sm[idx] = A[j];
        }
        __syncthreads();
        const int col = t & 127, rr = t >> 7;
        float a0 = 0.f, a1 = 0.f, a2 = 0.f, a3 = 0.f;
        if (r0 < 640) {
            const float* Bm = (r0 < 384) ? Wmq : (r0 < 512) ? Wmk : Wmv;
#pragma unroll 8
            for (int j = 0; j < DD; j++) {
                float bv = Bm[j * DD + col];
                a0 = fmaf(a_sm[(rr + 0) * DD + j], bv, a0);
                a1 = fmaf(a_sm[(rr + 2) * DD + j], bv, a1);
                a2 = fmaf(a_sm[(rr + 4) * DD + j], bv, a2);
                a3 = fmaf(a_sm[(rr + 6) * DD + j], bv, a3);
            }
        } else {
            // ZW[m][i] = sum_j Wmo[m][j] * Wks[i][j]; col = i
#pragma unroll 4
            for (int j = 0; j < DD; j += 4) {
                float4 wv = *(const float4*)(Wks + (size_t)col * DD + j);
                a0 = fmaf(a_sm[(rr + 0) * DD + j],     wv.x, a0);
                a0 = fmaf(a_sm[(rr + 0) * DD + j + 1], wv.y, a0);
                a0 = fmaf(a_sm[(rr + 0) * DD + j + 2], wv.z, a0);
                a0 = fmaf(a_sm[(rr + 0) * DD + j + 3], wv.w, a0);
                a1 = fmaf(a_sm[(rr + 2) * DD + j],     wv.x, a1);
                a1 = fmaf(a_sm[(rr + 2) * DD + j + 1], wv.y, a1);
                a1 = fmaf(a_sm[(rr + 2) * DD + j + 2], wv.z, a1);
                a1 = fmaf(a_sm[(rr + 2) * DD + j + 3], wv.w, a1);
                a2 = fmaf(a_sm[(rr + 4) * DD + j],     wv.x, a2);
                a2 = fmaf(a_sm[(rr + 4) * DD + j + 1], wv.y, a2);
                a2 = fmaf(a_sm[(rr + 4) * DD + j + 2], wv.z, a2);
                a2 = fmaf(a_sm[(rr + 4) * DD + j + 3], wv.w, a2);
                a3 = fmaf(a_sm[(rr + 6) * DD + j],     wv.x, a3);
                a3 = fmaf(a_sm[(rr + 6) * DD + j + 1], wv.y, a3);
                a3 = fmaf(a_sm[(rr + 6) * DD + j + 2], wv.z, a3);
                a3 = fmaf(a_sm[(rr + 6) * DD + j + 3], wv.w, a3);
            }
        }
        if (r0 >= 384 && r0 < 512) {
            // Z region: store TRANSPOSED (Zt[k][i]); k = col, i = output row
            int ib = r0 - 384 + rr;
            float* zt = g_fold + (size_t)(384 + col) * DD;
            zt[ib + 0] = a0;
            zt[ib + 2] = a1;
            zt[ib + 4] = a2;
            zt[ib + 6] = a3;
        } else {
            g_fold[(size_t)(r0 + rr + 0) * DD + col] = a0;
            g_fold[(size_t)(r0 + rr + 2) * DD + col] = a1;
            g_fold[(size_t)(r0 + rr + 4) * DD + col] = a2;
            g_fold[(size_t)(r0 + rr + 6) * DD + col] = a3;
        }
        return;
    }

    // ---------------- means path ----------------
    const int bs = blockIdx.x - PRE_CTAS;
    const int b = bs / SPLIT;
    const int s = bs % SPLIT;

    const long long mbase = (long long)b * NN + s * CH;
    for (int n = t; n < CH; n += 256) {
        mloc[n]  = rdmask(maskp,  flag, mbase + n) ? 1 : 0;
        cmloc[n] = rdmask(cmaskp, flag, mbase + n) ? 1 : 0;
    }
    __syncthreads();

    const float* np_ = node + ((size_t)b * NN + (size_t)s * CH) * DD;
    const int d0 = lane * 4;
    float4 a1 = make_float4(0.f, 0.f, 0.f, 0.f);
    float4 a2 = make_float4(0.f, 0.f, 0.f, 0.f);
#pragma unroll 6
    for (int n = w; n < CH; n += 8) {
        float4 v = __ldcs((const float4*)(np_ + (size_t)n * DD + d0));
        bool m = mloc[n] != 0;
        bool mc = (mloc[n] | cmloc[n]) != 0;
        if (!m)  { a1.x += v.x; a1.y += v.y; a1.z += v.z; a1.w += v.w; }
        if (!mc) { a2.x += v.x; a2.y += v.y; a2.z += v.z; a2.w += v.w; }
    }
    int o = w * 128 + d0;
    red[o] = a1.x; red[o + 1] = a1.y; red[o + 2] = a1.z; red[o + 3] = a1.w;
    red[1024 + o] = a2.x; red[1024 + o + 1] = a2.y;
    red[1024 + o + 2] = a2.z; red[1024 + o + 3] = a2.w;
    __syncthreads();
    if (t < DD) {
        float s1 = 0.f, s2 = 0.f;
#pragma unroll
        for (int ww = 0; ww < 8; ww++) {
            s1 += red[ww * 128 + t];
            s2 += red[1024 + ww * 128 + t];
        }
        size_t idx = (size_t)(b * SPLIT + s) * DD + t;
        g_part[idx] = s1;
        g_part[G2OFF + idx] = s2;
    }
}

// ============================================================================
// Kernel 2: per-batch fused compute. R11 base + L2 prefetch of g_fold +
// warp-local QH/GV reductions (2 fewer barriers). grid = B, block = 512.
// ============================================================================
__global__ void __launch_bounds__(512, 1)
clu_fused_kernel(const float* __restrict__ depot, const float* __restrict__ cluster,
                 const float* __restrict__ curE,
                 const void* __restrict__ isnewp,
                 const void* __restrict__ vcmp, const void* __restrict__ maskp,
                 float* __restrict__ out) {
    extern __shared__ float sm[];
    const int b = blockIdx.x;
    const int t = threadIdx.x;
    const int lane = t & 31;
    const int w = t >> 5;
    const int c4 = lane * 4;

    // ---- L2 prefetch of g_fold (384 KB = 3072 lines; 6 lines/thread) ----
    {
        const char* gf = (const char*)g_fold;
#pragma unroll
        for (int j = 0; j < 6; j++) {
            const char* p = gf + (size_t)(t + 512 * j) * 128;
            asm volatile("prefetch.global.L2 [%0];" :: "l"(p));
        }
    }

    // sniff bool dtype
    unsigned wword = ((const unsigned*)maskp)[t];
    int o1  = __syncthreads_or((wword & 0x0000ff00u) ? 1 : 0);
    int o23 = __syncthreads_or((wword & 0xffff0000u) ? 1 : 0);
    const int flag = o1 ? 0 : (o23 ? 2 : 1);
    const bool isnew = rdmask(isnewp, flag, b);

    // ===== P0: means reduce (t<128), small loads, cluster tile ==============
    if (t < DD) {
        float s1 = 0.f, s2 = 0.f;
#pragma unroll
        for (int s = 0; s < SPLIT; s++) {
            size_t idx = (size_t)(b * SPLIT + s) * DD + t;
            s1 += g_part[idx];
            s2 += g_part[G2OFF + idx];
        }
        float cu = curE[b * DD + t];
        float de = depot[b * DD + t];
        sm[S_CUR + t] = cu;
        sm[S_DEP + t] = de;
        sm[S_M2 + t] = s2 * (1.0f / NN);
        sm[S_CTX + t] = s1 * (1.0f / NN);
        sm[S_CTX + 128 + t] = cu;
        sm[S_CTX + 256 + t] = de;
    }
    if (t < CC) sm[S_VCM + t] = rdmask(vcmp, flag, (long long)b * CC + t) ? 1.0f : 0.0f;
    {
        const float* cp = cluster + (size_t)b * CC * DD;
        for (int p4 = t; p4 < (CC * DD) / 4; p4 += 512) {
            float4 v = ((const float4*)cp)[p4];
            int base = p4 * 4;
            float* dst = sm + S_CS + (base >> 7) * 129 + (base & 127);
            dst[0] = v.x; dst[1] = v.y; dst[2] = v.z; dst[3] = v.w;
        }
    }
    __syncthreads();

    // ===== P1: qh partials — warp w takes 24 rows of PQ =====================
    {
        float4 acc = make_float4(0.f, 0.f, 0.f, 0.f);
        int r0 = w * 24;
#pragma unroll 6
        for (int r = r0; r < r0 + 24; r++) {
            float4 pv = *(const float4*)(g_fold + (size_t)r * DD + c4);
            float cx = sm[S_CTX + r];
            acc.x = fmaf(cx, pv.x, acc.x);
            acc.y = fmaf(cx, pv.y, acc.y);
            acc.z = fmaf(cx, pv.z, acc.z);
            acc.w = fmaf(cx, pv.w, acc.w);
        }
        *(float4*)(sm + S_PB + w * 132 + c4) = acc;
        if (w == 15) {  // vcm[0] adjustment
            bool ok = true;
            for (int c = 1 + lane; c < CC; c += 32) ok = ok && (sm[S_VCM + c] != 0.0f);
            bool allv = __all_sync(0xffffffffu, ok);
            if (lane == 0 && isnew) sm[S_VCM + 0] = allv ? 0.0f : 1.0f;
        }
    }
    __syncthreads();

    // ===== P3: warps 0-7: warp-local QH reduce + u[i][h] from Zt (L2) =======
    if (w < 8) {
        const int qidx = 16 * w + (lane & 15);
        float qh_l = 0.f;
#pragma unroll
        for (int ww = 0; ww < 16; ww++) qh_l += sm[S_PB + ww * 132 + qidx];

        const float* Zt = g_fold + 384 * DD;
        float4 acc = make_float4(0.f, 0.f, 0.f, 0.f);
#pragma unroll
        for (int k = 0; k < 16; k++) {
            float q = __shfl_sync(0xffffffffu, qh_l, k);
            float4 zv = *(const float4*)(Zt + (size_t)(16 * w + k) * DD + c4);
            acc.x = fmaf(q, zv.x, acc.x);
            acc.y = fmaf(q, zv.y, acc.y);
            acc.z = fmaf(q, zv.z, acc.z);
            acc.w = fmaf(q, zv.w, acc.w);
        }
        sm[S_U4 + (c4 + 0) * 8 + w] = acc.x;
        sm[S_U4 + (c4 + 1) * 8 + w] = acc.y;
        sm[S_U4 + (c4 + 2) * 8 + w] = acc.z;
        sm[S_U4 + (c4 + 3) * 8 + w] = acc.w;
    }
    __syncthreads();

    // ===== P4: score partials (t<200: c, half) ==============================
    if (t < 2 * CC) {
        int c = t >> 1, half = t & 1, i0 = half * 64;
        float acc[8] = {0.f, 0.f, 0.f, 0.f, 0.f, 0.f, 0.f, 0.f};
#pragma unroll 4
        for (int i = i0; i < i0 + 64; i++) {
            float cv = sm[S_CS + c * 129 + i];
            float4 u0 = *(const float4*)(sm + S_U4 + i * 8);
            float4 u1 = *(const float4*)(sm + S_U4 + i * 8 + 4);
            acc[0] = fmaf(cv, u0.x, acc[0]);
            acc[1] = fmaf(cv, u0.y, acc[1]);
            acc[2] = fmaf(cv, u0.z, acc[2]);
            acc[3] = fmaf(cv, u0.w, acc[3]);
            acc[4] = fmaf(cv, u1.x, acc[4]);
            acc[5] = fmaf(cv, u1.y, acc[5]);
            acc[6] = fmaf(cv, u1.z, acc[6]);
            acc[7] = fmaf(cv, u1.w, acc[7]);
        }
#pragma unroll
        for (int h = 0; h < HH; h++) sm[S_SCP + c * 16 + half * 8 + h] = acc[h];
    }
    __syncthreads();

    // ===== P5: softmax — warp w (<8) handles head h=w ========================
    if (w < 8) {
        int h = w;
        float vv[4];
        float mx = -INFINITY;
#pragma unroll
        for (int idx = 0; idx < 4; idx++) {
            int c = lane + 32 * idx;
            float val = -INFINITY;
            if (c < CC) {
                float scv = sm[S_SCP + c * 16 + h] + sm[S_SCP + c * 16 + 8 + h];
                val = (sm[S_VCM + c] != 0.0f) ? NEGV : scv * 0.25f;
            }
            vv[idx] = val;
            mx = fmaxf(mx, val);
        }
#pragma unroll
        for (int off = 16; off; off >>= 1)
            mx = fmaxf(mx, __shfl_xor_sync(0xffffffffu, mx, off));
        float ssum = 0.f;
#pragma unroll
        for (int idx = 0; idx < 4; idx++) {
            int c = lane + 32 * idx;
            if (c < CC) {
                float e = expf(vv[idx] - mx);
                ssum += e;
                vv[idx] = e;
            }
        }
#pragma unroll
        for (int off = 16; off; off >>= 1)
            ssum += __shfl_xor_sync(0xffffffffu, ssum, off);
        float inv = 1.0f / ssum;
#pragma unroll
        for (int idx = 0; idx < 4; idx++) {
            int c = lane + 32 * idx;
            if (c < CC) sm[S_AT4 + c * 8 + h] = vv[idx] * inv;
        }
    }
    __syncthreads();

    // ===== P6: wsum[h][i] = sum_c attn[h][c]*cluster[c][i] (t<256) ===========
    if (t < 256) {
        int i = t & 127, par = t >> 7;
        float acc[4] = {0.f, 0.f, 0.f, 0.f};
#pragma unroll 4
        for (int c = 0; c < CC; c++) {
            float cv = sm[S_CS + c * 129 + i];
            float4 av = *(const float4*)(sm + S_AT4 + c * 8 + par * 4);
            acc[0] = fmaf(av.x, cv, acc[0]);
            acc[1] = fmaf(av.y, cv, acc[1]);
            acc[2] = fmaf(av.z, cv, acc[2]);
            acc[3] = fmaf(av.w, cv, acc[3]);
        }
        *(float4*)(sm + S_WS4 + i * 8 + par * 4) =
            make_float4(acc[0], acc[1], acc[2], acc[3]);
    }
    __syncthreads();

    // ===== P7: gv partials — warp w takes 8 rows of ZV (L2) ==================
    {
        const float* ZV = g_fold + 512 * DD;
        const int hsel = lane >> 2;
        float4 acc = make_float4(0.f, 0.f, 0.f, 0.f);
#pragma unroll
        for (int ii = 0; ii < 8; ii++) {
            int i = w * 8 + ii;
            float4 zv = *(const float4*)(ZV + (size_t)i * DD + c4);
            float s = sm[S_WS4 + i * 8 + hsel];
            acc.x = fmaf(s, zv.x, acc.x);
            acc.y = fmaf(s, zv.y, acc.y);
            acc.z = fmaf(s, zv.z, acc.z);
            acc.w = fmaf(s, zv.w, acc.w);
        }
        *(float4*)(sm + S_PB + w * 132 + c4) = acc;
    }
    __syncthreads();

    // ===== P9: warp-local GV reduce + gw partials from ZW (L2) ===============
    {
        const int gidx = 8 * w + (lane & 7);
        float gv_l = 0.f;
#pragma unroll
        for (int ww = 0; ww < 16; ww++) gv_l += sm[S_PB + ww * 132 + gidx];

        const float* ZW = g_fold + 640 * DD;
        float4 acc = make_float4(0.f, 0.f, 0.f, 0.f);
#pragma unroll
        for (int mm = 0; mm < 8; mm++) {
            float s = __shfl_sync(0xffffffffu, gv_l, mm);
            float4 zw = *(const float4*)(ZW + (size_t)(w * 8 + mm) * DD + c4);
            acc.x = fmaf(s, zw.x, acc.x);
            acc.y = fmaf(s, zw.y, acc.y);
            acc.z = fmaf(s, zw.z, acc.z);
            acc.w = fmaf(s, zw.w, acc.w);
        }
        *(float4*)(sm + S_PB2 + w * 132 + c4) = acc;
    }
    __syncthreads();

    // ===== P10: gw reduce ====================================================
    if (t < DD) {
        float s = 0.f;
#pragma unroll
        for (int ww = 0; ww < 16; ww++) s += sm[S_PB2 + ww * 132 + t];
        sm[S_GW + t] = s;
    }
    __syncthreads();

    // ===== P11: logit partials (t<200) =======================================
    if (t < 2 * CC) {
        int c = t >> 1, half = t & 1;
        float acc = 0.f;
        int i0 = half * 64;
#pragma unroll 8
        for (int i = i0; i < i0 + 64; i++)
            acc = fmaf(sm[S_CS + c * 129 + i], sm[S_GW + i], acc);
        sm[S_PART + c * 2 + half] = acc;
    }
    __syncthreads();

    // ===== P12: finalize logits + argmax + lse (warp 0) ======================
    if (w == 0) {
        float vv[4];
        float bv = -INFINITY;
        int bi = 0x7fffffff;
#pragma unroll
        for (int idx = 0; idx < 4; idx++) {
            int c = lane + 32 * idx;
            float val = -INFINITY;
            if (c < CC) {
                float lg = (sm[S_PART + c * 2] + sm[S_PART + c * 2 + 1])
                           * 0.08838834764831845f;
                lg = tanhf(lg) * CLIPV;
                val = (sm[S_VCM + c] != 0.0f) ? NEGV : lg;
                sm[S_LGT + c] = val;
                if (val > bv || (val == bv && c < bi)) { bv = val; bi = c; }
            }
            vv[idx] = val;
        }
#pragma unroll
        for (int off = 16; off; off >>= 1) {
            float ov = __shfl_down_sync(0xffffffffu, bv, off);
            int oi = __shfl_down_sync(0xffffffffu, bi, off);
            if (ov > bv || (ov == bv && oi < bi)) { bv = ov; bi = oi; }
        }
        bv = __shfl_sync(0xffffffffu, bv, 0);
        bi = __shfl_sync(0xffffffffu, bi, 0);
        float s = 0.f;
#pragma unroll
        for (int idx = 0; idx < 4; idx++) {
            int c = lane + 32 * idx;
            if (c < CC) s += expf(vv[idx] - bv);
        }
#pragma unroll
        for (int off = 16; off; off >>= 1) s += __shfl_xor_sync(0xffffffffu, s, off);
        if (lane == 0) {
            sm[S_MISC + 0] = (float)bi;
            sm[S_MISC + 1] = bv + logf(s);
        }
    }
    __syncthreads();

    // ===== P13: outputs ======================================================
    const int gid = (int)sm[S_MISC + 0];
    const float mlse = sm[S_MISC + 1];
    float* aug = out + OUT_AUG + (size_t)b * 512;
    float* gout = out + OUT_GEMB + (size_t)b * 128;
    float* cpo = out + OUT_CLU + (size_t)b * CC;
    if (t < DD) {
        float ge = sm[S_CS + gid * 129 + t];
        aug[t]        = isnew ? sm[S_M2 + t] : 0.0f;
        aug[128 + t]  = isnew ? sm[S_CUR + t] : 0.0f;
        aug[256 + t]  = isnew ? ge : 0.0f;
        aug[384 + t]  = isnew ? sm[S_DEP + t] : 0.0f;
        gout[t]       = isnew ? ge : 0.0f;
    }
    if (t >= 256 && t < 256 + CC) {
        int c = t - 256;
        cpo[c] = isnew ? (sm[S_LGT + c] - mlse) : 0.0f;
    }
    if (t == 511) out[OUT_GUID + b] = isnew ? (float)gid : 0.0f;
}

extern "C" void kernel_launch(void* const* d_in, const int* in_sizes, int n_in,
                              void* d_out, int out_size) {
    (void)in_sizes; (void)n_in; (void)out_size;
    const float* depot   = (const float*)d_in[0];
    const float* cluster = (const float*)d_in[1];
    const float* curE    = (const float*)d_in[2];
    const float* node    = (const float*)d_in[3];
    const void*  isnewp  = d_in[4];
    const void*  cmaskp  = d_in[5];
    const void*  vcmp    = d_in[6];
    const void*  maskp   = d_in[7];
    const float* Wq  = (const float*)d_in[8];
    const float* Wk  = (const float*)d_in[9];
    const float* Wv  = (const float*)d_in[10];
    const float* Wks = (const float*)d_in[11];
    const float* Wmq = (const float*)d_in[12];
    const float* Wmk = (const float*)d_in[13];
    const float* Wmv = (const float*)d_in[14];
    const float* Wmo = (const float*)d_in[15];

    means_pre_kernel<<<PRE_CTAS + BB * SPLIT, 256>>>(
        node, maskp, cmaskp, Wq, Wk, Wv, Wks, Wmq, Wmk, Wmv, Wmo);

    cudaFuncSetAttribute(clu_fused_kernel,
                         cudaFuncAttributeMaxDynamicSharedMemorySize, SMEM_BYTES);
    clu_fused_kernel<<<BB, 512, SMEM_BYTES>>>(
        depot, cluster, curE, isnewp, vcmp, maskp, (float*)d_out);
}